// round 4
// baseline (speedup 1.0000x reference)
#include <cuda_runtime.h>
#include <cstdint>
#include <math.h>

#define N_NODES 100000
#define N_EDGES 3200000
#define D_FEAT  512
#define HID     16

// ---------------- scratch (device globals; no allocation allowed) ----------
__device__ float g_t1[N_NODES * HID];   // x @ W1
__device__ float g_h1[N_NODES * HID];   // scatter accumulator layer 1
__device__ float g_t2[N_NODES * HID];   // relu(h1+b1) @ W2
__device__ int   g_is64;

// ---------------- helpers --------------------------------------------------
__device__ __forceinline__ unsigned long long ffma2(unsigned long long a,
                                                    unsigned long long b,
                                                    unsigned long long c) {
    unsigned long long d;
    asm("fma.rn.f32x2 %0, %1, %2, %3;" : "=l"(d) : "l"(a), "l"(b), "l"(c));
    return d;
}

// ---------------- edge_index dtype detection (parallel) --------------------
// If int64 with values in [0, N_NODES), every high 32-bit word is 0.
__global__ void detect_kernel(const void* eiv) {
    __shared__ int any32;
    if (threadIdx.x == 0) any32 = 0;
    __syncthreads();
    const int* p = (const int*)eiv;
    int local = 0;
    for (int i = threadIdx.x; i < 2048; i += 256)
        if (p[2 * i + 1] != 0) local = 1;
    if (local) atomicOr(&any32, 1);
    __syncthreads();
    if (threadIdx.x == 0) g_is64 = !any32;
}

// ---------------- zero accumulators ---------------------------------------
__global__ void zero_kernel(float* __restrict__ out) {
    int i = blockIdx.x * blockDim.x + threadIdx.x;
    const int total4 = N_NODES * HID / 4;   // 400000 float4s
    if (i < total4) {
        float4 z = make_float4(0.f, 0.f, 0.f, 0.f);
        ((float4*)g_h1)[i] = z;
        ((float4*)out)[i]  = z;
    }
}

// ---------------- GEMM1: t1 = x @ W1  (100000x512 @ 512x16) ---------------
// Block = 256 threads, 256 rows per block. K tiled by 8.
// FFMA2 (f32x2) packs two output columns per instruction.
#define KT 8
__global__ void gemm1_kernel(const float* __restrict__ x,
                             const float* __restrict__ W1) {
    __shared__ float Ws[D_FEAT * HID];       // 32 KB
    __shared__ float xs[256 * (KT + 1)];     // 9 KB, pad stride 9 (coprime 32)

    const int t = threadIdx.x;
    for (int i = t; i < D_FEAT * HID; i += 256) Ws[i] = W1[i];

    const int row0   = blockIdx.x * 256;
    const int my_row = row0 + t;

    unsigned long long acc[8];
#pragma unroll
    for (int j = 0; j < 8; j++) acc[j] = 0ULL;

    for (int kt = 0; kt < D_FEAT / KT; kt++) {
        const int k0 = kt * KT;
        __syncthreads();
        // stage 256 rows x 8 cols via LDG.128: 512 float4s, 2 per thread
#pragma unroll
        for (int i = 0; i < 2; i++) {
            int idx  = t + 256 * i;       // 0..511
            int r    = idx >> 1;          // row within tile
            int half = idx & 1;           // which float4 of the 8 cols
            int gr   = row0 + r;
            float4 v = make_float4(0.f, 0.f, 0.f, 0.f);
            if (gr < N_NODES)
                v = *(const float4*)(x + (size_t)gr * D_FEAT + k0 + half * 4);
            float* dst = xs + r * (KT + 1) + half * 4;
            dst[0] = v.x; dst[1] = v.y; dst[2] = v.z; dst[3] = v.w;
        }
        __syncthreads();

        const float* xrow = xs + t * (KT + 1);
#pragma unroll
        for (int kk = 0; kk < KT; kk++) {
            float xv = xrow[kk];
            unsigned long long xp;
            unsigned int xb = __float_as_uint(xv);
            asm("mov.b64 %0, {%1, %1};" : "=l"(xp) : "r"(xb));
            const ulonglong2* wrow =
                (const ulonglong2*)(Ws + (k0 + kk) * HID);
#pragma unroll
            for (int j2 = 0; j2 < 4; j2++) {
                ulonglong2 wp = wrow[j2];
                acc[2 * j2]     = ffma2(xp, wp.x, acc[2 * j2]);
                acc[2 * j2 + 1] = ffma2(xp, wp.y, acc[2 * j2 + 1]);
            }
        }
    }

    if (my_row < N_NODES) {
        float o[16];
#pragma unroll
        for (int j = 0; j < 8; j++) {
            unsigned int lo, hi;
            asm("mov.b64 {%0, %1}, %2;" : "=r"(lo), "=r"(hi) : "l"(acc[j]));
            o[2 * j]     = __uint_as_float(lo);
            o[2 * j + 1] = __uint_as_float(hi);
        }
        float4* dst = (float4*)(g_t1 + (size_t)my_row * HID);
        dst[0] = make_float4(o[0], o[1], o[2], o[3]);
        dst[1] = make_float4(o[4], o[5], o[6], o[7]);
        dst[2] = make_float4(o[8], o[9], o[10], o[11]);
        dst[3] = make_float4(o[12], o[13], o[14], o[15]);
    }
}

// ---------------- edge scatter: acc[dst] += w * feat[src] ------------------
// One thread per edge: 4 independent LDG.128 (MLP=4) + 4 RED.128.
__global__ void scatter_kernel(const void* __restrict__ eiv,
                               const float* __restrict__ ew,
                               float* __restrict__ out, int pass) {
    int e = blockIdx.x * blockDim.x + threadIdx.x;
    if (e >= N_EDGES) return;

    const float* feat = (pass == 0) ? g_t1 : g_t2;
    float*       acc  = (pass == 0) ? g_h1 : out;

    int s, d;
    if (!g_is64) {
        const int* ei = (const int*)eiv;
        s = ei[e];
        d = ei[N_EDGES + e];
    } else {
        const long long* ei = (const long long*)eiv;
        s = (int)ei[e];
        d = (int)ei[N_EDGES + e];
    }
    float w = ew[e];

    const float4* src4 = (const float4*)(feat + (size_t)s * HID);
    float4 v0 = src4[0];
    float4 v1 = src4[1];
    float4 v2 = src4[2];
    float4 v3 = src4[3];

    float4* dst4 = (float4*)(acc + (size_t)d * HID);
    atomicAdd(dst4 + 0, make_float4(w * v0.x, w * v0.y, w * v0.z, w * v0.w));
    atomicAdd(dst4 + 1, make_float4(w * v1.x, w * v1.y, w * v1.z, w * v1.w));
    atomicAdd(dst4 + 2, make_float4(w * v2.x, w * v2.y, w * v2.z, w * v2.w));
    atomicAdd(dst4 + 3, make_float4(w * v3.x, w * v3.y, w * v3.z, w * v3.w));
}

// ---------------- mid: t2 = relu(h1 + b1) @ W2 -----------------------------
__global__ void mid_kernel(const float* __restrict__ b1,
                           const float* __restrict__ W2) {
    __shared__ float W2s[HID * HID];
    __shared__ float b1s[HID];
    int t = threadIdx.x;
    if (t < HID * HID) W2s[t] = W2[t];
    if (t < HID) b1s[t] = b1[t];
    __syncthreads();

    int node = blockIdx.x * blockDim.x + t;
    if (node >= N_NODES) return;

    float v[16];
    const float4* src = (const float4*)(g_h1 + (size_t)node * HID);
#pragma unroll
    for (int q = 0; q < 4; q++) {
        float4 f = src[q];
        v[4 * q] = f.x; v[4 * q + 1] = f.y; v[4 * q + 2] = f.z; v[4 * q + 3] = f.w;
    }
#pragma unroll
    for (int i = 0; i < 16; i++) v[i] = fmaxf(v[i] + b1s[i], 0.0f);

    float o[16];
#pragma unroll
    for (int j = 0; j < 16; j++) o[j] = 0.0f;
#pragma unroll
    for (int i = 0; i < 16; i++) {
        float vi = v[i];
#pragma unroll
        for (int j = 0; j < 16; j++) o[j] = fmaf(vi, W2s[i * 16 + j], o[j]);
    }

    float4* dst = (float4*)(g_t2 + (size_t)node * HID);
    dst[0] = make_float4(o[0], o[1], o[2], o[3]);
    dst[1] = make_float4(o[4], o[5], o[6], o[7]);
    dst[2] = make_float4(o[8], o[9], o[10], o[11]);
    dst[3] = make_float4(o[12], o[13], o[14], o[15]);
}

// ---------------- final: out = log_softmax(out + b2) -----------------------
__global__ void final_kernel(float* __restrict__ out,
                             const float* __restrict__ b2) {
    __shared__ float b2s[HID];
    if (threadIdx.x < HID) b2s[threadIdx.x] = b2[threadIdx.x];
    __syncthreads();

    int node = blockIdx.x * blockDim.x + threadIdx.x;
    if (node >= N_NODES) return;

    float o[16];
    float4* p = (float4*)(out + (size_t)node * HID);
#pragma unroll
    for (int q = 0; q < 4; q++) {
        float4 f = p[q];
        o[4 * q]     = f.x + b2s[4 * q];
        o[4 * q + 1] = f.y + b2s[4 * q + 1];
        o[4 * q + 2] = f.z + b2s[4 * q + 2];
        o[4 * q + 3] = f.w + b2s[4 * q + 3];
    }
    float m = o[0];
#pragma unroll
    for (int j = 1; j < 16; j++) m = fmaxf(m, o[j]);
    float ssum = 0.0f;
#pragma unroll
    for (int j = 0; j < 16; j++) ssum += expf(o[j] - m);
    float lse = m + logf(ssum);
#pragma unroll
    for (int j = 0; j < 16; j++) o[j] -= lse;

    p[0] = make_float4(o[0], o[1], o[2], o[3]);
    p[1] = make_float4(o[4], o[5], o[6], o[7]);
    p[2] = make_float4(o[8], o[9], o[10], o[11]);
    p[3] = make_float4(o[12], o[13], o[14], o[15]);
}

// ---------------- launch ---------------------------------------------------
extern "C" void kernel_launch(void* const* d_in, const int* in_sizes, int n_in,
                              void* d_out, int out_size) {
    const float* x  = (const float*)d_in[0];
    const void*  ei = d_in[1];
    const float* ew = (const float*)d_in[2];
    const float* W1 = (const float*)d_in[3];
    const float* b1 = (const float*)d_in[4];
    const float* W2 = (const float*)d_in[5];
    const float* b2 = (const float*)d_in[6];
    float* out = (float*)d_out;

    detect_kernel<<<1, 256>>>(ei);
    zero_kernel<<<(N_NODES * HID / 4 + 255) / 256, 256>>>(out);
    gemm1_kernel<<<(N_NODES + 255) / 256, 256>>>(x, W1);

    const int eb = (N_EDGES + 255) / 256;
    scatter_kernel<<<eb, 256>>>(ei, ew, out, 0);
    mid_kernel<<<(N_NODES + 255) / 256, 256>>>(b1, W2);
    scatter_kernel<<<eb, 256>>>(ei, ew, out, 1);
    final_kernel<<<(N_NODES + 255) / 256, 256>>>(out, b2);
}

// round 5
// speedup vs baseline: 1.2292x; 1.2292x over previous
#include <cuda_runtime.h>
#include <cstdint>
#include <math.h>

#define N_NODES 100000
#define N_EDGES 3200000
#define D_FEAT  512
#define HID     16

#define SCAN_BLOCKS 100
#define SCAN_ELEMS  1000   // SCAN_BLOCKS * SCAN_ELEMS = N_NODES

// ---------------- scratch (device globals; no allocation allowed) ----------
__device__ float g_t1[N_NODES * HID];   // x @ W1
__device__ float g_h1[N_NODES * HID];   // layer-1 aggregated
__device__ float g_t2[N_NODES * HID];   // relu(h1+b1) @ W2
__device__ int   g_cnt[N_NODES];        // in-degree
__device__ int   g_cur[N_NODES];        // fill cursor
__device__ int   g_off[N_NODES];        // CSR offsets
__device__ int   g_bsum[SCAN_BLOCKS];
__device__ int2  g_adj[N_EDGES];        // {src, weight_bits} grouped by dst
__device__ int   g_is64;

// ---------------- helpers --------------------------------------------------
__device__ __forceinline__ unsigned long long ffma2(unsigned long long a,
                                                    unsigned long long b,
                                                    unsigned long long c) {
    unsigned long long d;
    asm("fma.rn.f32x2 %0, %1, %2, %3;" : "=l"(d) : "l"(a), "l"(b), "l"(c));
    return d;
}

// ---------------- edge_index dtype detection (parallel) --------------------
__global__ void detect_kernel(const void* eiv) {
    __shared__ int any32;
    if (threadIdx.x == 0) any32 = 0;
    __syncthreads();
    const int* p = (const int*)eiv;
    int local = 0;
    for (int i = threadIdx.x; i < 2048; i += 256)
        if (p[2 * i + 1] != 0) local = 1;
    if (local) atomicOr(&any32, 1);
    __syncthreads();
    if (threadIdx.x == 0) g_is64 = !any32;
}

// ---------------- zero counters -------------------------------------------
__global__ void zero_cnt_kernel() {
    int i = blockIdx.x * blockDim.x + threadIdx.x;
    if (i < N_NODES) { g_cnt[i] = 0; g_cur[i] = 0; }
}

// ---------------- histogram of dst ----------------------------------------
__global__ void hist_kernel(const void* __restrict__ eiv) {
    int e = blockIdx.x * blockDim.x + threadIdx.x;
    if (e >= N_EDGES) return;
    int d;
    if (!g_is64) d = ((const int*)eiv)[N_EDGES + e];
    else         d = (int)((const long long*)eiv)[N_EDGES + e];
    atomicAdd(&g_cnt[d], 1);
}

// ---------------- scan phase 1: per-block sums (warp reduce) ---------------
__global__ void scan1_kernel() {
    __shared__ int wsum[32];
    int b = blockIdx.x, t = threadIdx.x;
    int lane = t & 31, wid = t >> 5;
    int v = (t < SCAN_ELEMS) ? g_cnt[b * SCAN_ELEMS + t] : 0;
#pragma unroll
    for (int o = 16; o > 0; o >>= 1) v += __shfl_down_sync(~0u, v, o);
    if (lane == 0) wsum[wid] = v;
    __syncthreads();
    if (wid == 0) {
        int s = wsum[lane];
#pragma unroll
        for (int o = 16; o > 0; o >>= 1) s += __shfl_down_sync(~0u, s, o);
        if (lane == 0) g_bsum[b] = s;
    }
}

// ---------------- scan phase 2: exclusive scan of 100 block sums -----------
__global__ void scan2_kernel() {
    if (threadIdx.x == 0) {
        int run = 0;
        for (int i = 0; i < SCAN_BLOCKS; i++) {
            int v = g_bsum[i]; g_bsum[i] = run; run += v;
        }
    }
}

// ---------------- scan phase 3: intra-block exclusive scan (shfl) ----------
__global__ void scan3_kernel() {
    __shared__ int wsum[32];
    int b = blockIdx.x, t = threadIdx.x;
    int lane = t & 31, wid = t >> 5;
    int orig = (t < SCAN_ELEMS) ? g_cnt[b * SCAN_ELEMS + t] : 0;
    int v = orig;
#pragma unroll
    for (int o = 1; o < 32; o <<= 1) {
        int n = __shfl_up_sync(~0u, v, o);
        if (lane >= o) v += n;
    }
    if (lane == 31) wsum[wid] = v;
    __syncthreads();
    if (wid == 0) {
        int s = wsum[lane];
#pragma unroll
        for (int o = 1; o < 32; o <<= 1) {
            int n = __shfl_up_sync(~0u, s, o);
            if (lane >= o) s += n;
        }
        wsum[lane] = s;   // inclusive warp sums
    }
    __syncthreads();
    int woff = (wid == 0) ? 0 : wsum[wid - 1];
    if (t < SCAN_ELEMS)
        g_off[b * SCAN_ELEMS + t] = (v - orig) + woff + g_bsum[b];
}

// ---------------- fill CSR adjacency ---------------------------------------
__global__ void fill_kernel(const void* __restrict__ eiv,
                            const float* __restrict__ ew) {
    int e = blockIdx.x * blockDim.x + threadIdx.x;
    if (e >= N_EDGES) return;
    int s, d;
    if (!g_is64) {
        const int* ei = (const int*)eiv;
        s = ei[e]; d = ei[N_EDGES + e];
    } else {
        const long long* ei = (const long long*)eiv;
        s = (int)ei[e]; d = (int)ei[N_EDGES + e];
    }
    float w = ew[e];
    int pos = g_off[d] + atomicAdd(&g_cur[d], 1);
    g_adj[pos] = make_int2(s, __float_as_int(w));
}

// ---------------- GEMM1: t1 = x @ W1  (100000x512 @ 512x16) ---------------
#define KT 8
__global__ void gemm1_kernel(const float* __restrict__ x,
                             const float* __restrict__ W1) {
    __shared__ float Ws[D_FEAT * HID];       // 32 KB
    __shared__ float xs[256 * (KT + 1)];     // 9 KB

    const int t = threadIdx.x;
    for (int i = t; i < D_FEAT * HID; i += 256) Ws[i] = W1[i];

    const int row0   = blockIdx.x * 256;
    const int my_row = row0 + t;

    unsigned long long acc[8];
#pragma unroll
    for (int j = 0; j < 8; j++) acc[j] = 0ULL;

    for (int kt = 0; kt < D_FEAT / KT; kt++) {
        const int k0 = kt * KT;
        __syncthreads();
#pragma unroll
        for (int i = 0; i < KT; i++) {
            int idx = t + 256 * i;
            int r = idx >> 3;
            int kk = idx & 7;
            int gr = row0 + r;
            xs[r * (KT + 1) + kk] =
                (gr < N_NODES) ? x[(size_t)gr * D_FEAT + k0 + kk] : 0.0f;
        }
        __syncthreads();

        const float* xrow = xs + t * (KT + 1);
#pragma unroll
        for (int kk = 0; kk < KT; kk++) {
            float xv = xrow[kk];
            unsigned long long xp;
            unsigned int xb = __float_as_uint(xv);
            asm("mov.b64 %0, {%1, %1};" : "=l"(xp) : "r"(xb));
            const ulonglong2* wrow =
                (const ulonglong2*)(Ws + (k0 + kk) * HID);
#pragma unroll
            for (int j2 = 0; j2 < 4; j2++) {
                ulonglong2 wp = wrow[j2];
                acc[2 * j2]     = ffma2(xp, wp.x, acc[2 * j2]);
                acc[2 * j2 + 1] = ffma2(xp, wp.y, acc[2 * j2 + 1]);
            }
        }
    }

    if (my_row < N_NODES) {
        float o[16];
#pragma unroll
        for (int j = 0; j < 8; j++) {
            unsigned int lo, hi;
            asm("mov.b64 {%0, %1}, %2;" : "=r"(lo), "=r"(hi) : "l"(acc[j]));
            o[2 * j]     = __uint_as_float(lo);
            o[2 * j + 1] = __uint_as_float(hi);
        }
        float4* dst = (float4*)(g_t1 + (size_t)my_row * HID);
        dst[0] = make_float4(o[0], o[1], o[2], o[3]);
        dst[1] = make_float4(o[4], o[5], o[6], o[7]);
        dst[2] = make_float4(o[8], o[9], o[10], o[11]);
        dst[3] = make_float4(o[12], o[13], o[14], o[15]);
    }
}

// ---------------- CSR gather: acc[n] = sum_e w_e * feat[src_e] -------------
// 4 lanes per node (one float4 chunk each); edge loop unrolled x4 for MLP.
// Grid: 3125 blocks x 128 threads = 12500 warps = exactly 100000 nodes.
__global__ void __launch_bounds__(128) gather_kernel(float* __restrict__ out,
                                                     int pass) {
    int warp_id = (blockIdx.x * blockDim.x + threadIdx.x) >> 5;
    int lane = threadIdx.x & 31;
    int g = lane >> 2;       // node slot within warp (0..7)
    int c = lane & 3;        // float4 chunk (0..3)
    int node = warp_id * 8 + g;
    if (node >= N_NODES) return;

    const float* feat = (pass == 0) ? g_t1 : g_t2;
    float*       acc  = (pass == 0) ? g_h1 : out;

    int beg = g_off[node];
    int deg = g_cnt[node];

    float4 s = make_float4(0.f, 0.f, 0.f, 0.f);
    int i = 0;
    for (; i + 4 <= deg; i += 4) {
        // 4 independent adj loads (broadcast within the 4-lane group)
        int2 e0 = g_adj[beg + i];
        int2 e1 = g_adj[beg + i + 1];
        int2 e2 = g_adj[beg + i + 2];
        int2 e3 = g_adj[beg + i + 3];
        // 4 independent feature gathers
        float4 v0 = *(const float4*)(feat + (size_t)e0.x * HID + c * 4);
        float4 v1 = *(const float4*)(feat + (size_t)e1.x * HID + c * 4);
        float4 v2 = *(const float4*)(feat + (size_t)e2.x * HID + c * 4);
        float4 v3 = *(const float4*)(feat + (size_t)e3.x * HID + c * 4);
        float w0 = __int_as_float(e0.y), w1 = __int_as_float(e1.y);
        float w2 = __int_as_float(e2.y), w3 = __int_as_float(e3.y);
        s.x = fmaf(w0, v0.x, s.x); s.y = fmaf(w0, v0.y, s.y);
        s.z = fmaf(w0, v0.z, s.z); s.w = fmaf(w0, v0.w, s.w);
        s.x = fmaf(w1, v1.x, s.x); s.y = fmaf(w1, v1.y, s.y);
        s.z = fmaf(w1, v1.z, s.z); s.w = fmaf(w1, v1.w, s.w);
        s.x = fmaf(w2, v2.x, s.x); s.y = fmaf(w2, v2.y, s.y);
        s.z = fmaf(w2, v2.z, s.z); s.w = fmaf(w2, v2.w, s.w);
        s.x = fmaf(w3, v3.x, s.x); s.y = fmaf(w3, v3.y, s.y);
        s.z = fmaf(w3, v3.z, s.z); s.w = fmaf(w3, v3.w, s.w);
    }
    for (; i < deg; i++) {
        int2 e = g_adj[beg + i];
        float w = __int_as_float(e.y);
        float4 v = *(const float4*)(feat + (size_t)e.x * HID + c * 4);
        s.x = fmaf(w, v.x, s.x); s.y = fmaf(w, v.y, s.y);
        s.z = fmaf(w, v.z, s.z); s.w = fmaf(w, v.w, s.w);
    }
    *(float4*)(acc + (size_t)node * HID + c * 4) = s;
}

// ---------------- mid: t2 = relu(h1 + b1) @ W2 -----------------------------
__global__ void mid_kernel(const float* __restrict__ b1,
                           const float* __restrict__ W2) {
    __shared__ float W2s[HID * HID];
    __shared__ float b1s[HID];
    int t = threadIdx.x;
    if (t < HID * HID) W2s[t] = W2[t];
    if (t < HID) b1s[t] = b1[t];
    __syncthreads();

    int node = blockIdx.x * blockDim.x + t;
    if (node >= N_NODES) return;

    float v[16];
    const float4* src = (const float4*)(g_h1 + (size_t)node * HID);
#pragma unroll
    for (int q = 0; q < 4; q++) {
        float4 f = src[q];
        v[4 * q] = f.x; v[4 * q + 1] = f.y; v[4 * q + 2] = f.z; v[4 * q + 3] = f.w;
    }
#pragma unroll
    for (int i = 0; i < 16; i++) v[i] = fmaxf(v[i] + b1s[i], 0.0f);

    float o[16];
#pragma unroll
    for (int j = 0; j < 16; j++) o[j] = 0.0f;
#pragma unroll
    for (int i = 0; i < 16; i++) {
        float vi = v[i];
#pragma unroll
        for (int j = 0; j < 16; j++) o[j] = fmaf(vi, W2s[i * 16 + j], o[j]);
    }

    float4* dst = (float4*)(g_t2 + (size_t)node * HID);
    dst[0] = make_float4(o[0], o[1], o[2], o[3]);
    dst[1] = make_float4(o[4], o[5], o[6], o[7]);
    dst[2] = make_float4(o[8], o[9], o[10], o[11]);
    dst[3] = make_float4(o[12], o[13], o[14], o[15]);
}

// ---------------- final: out = log_softmax(out + b2) -----------------------
__global__ void final_kernel(float* __restrict__ out,
                             const float* __restrict__ b2) {
    __shared__ float b2s[HID];
    if (threadIdx.x < HID) b2s[threadIdx.x] = b2[threadIdx.x];
    __syncthreads();

    int node = blockIdx.x * blockDim.x + threadIdx.x;
    if (node >= N_NODES) return;

    float o[16];
    float4* p = (float4*)(out + (size_t)node * HID);
#pragma unroll
    for (int q = 0; q < 4; q++) {
        float4 f = p[q];
        o[4 * q]     = f.x + b2s[4 * q];
        o[4 * q + 1] = f.y + b2s[4 * q + 1];
        o[4 * q + 2] = f.z + b2s[4 * q + 2];
        o[4 * q + 3] = f.w + b2s[4 * q + 3];
    }
    float m = o[0];
#pragma unroll
    for (int j = 1; j < 16; j++) m = fmaxf(m, o[j]);
    float ssum = 0.0f;
#pragma unroll
    for (int j = 0; j < 16; j++) ssum += expf(o[j] - m);
    float lse = m + logf(ssum);
#pragma unroll
    for (int j = 0; j < 16; j++) o[j] -= lse;

    p[0] = make_float4(o[0], o[1], o[2], o[3]);
    p[1] = make_float4(o[4], o[5], o[6], o[7]);
    p[2] = make_float4(o[8], o[9], o[10], o[11]);
    p[3] = make_float4(o[12], o[13], o[14], o[15]);
}

// ---------------- launch ---------------------------------------------------
extern "C" void kernel_launch(void* const* d_in, const int* in_sizes, int n_in,
                              void* d_out, int out_size) {
    const float* x  = (const float*)d_in[0];
    const void*  ei = d_in[1];
    const float* ew = (const float*)d_in[2];
    const float* W1 = (const float*)d_in[3];
    const float* b1 = (const float*)d_in[4];
    const float* W2 = (const float*)d_in[5];
    const float* b2 = (const float*)d_in[6];
    float* out = (float*)d_out;

    const int eb = (N_EDGES + 255) / 256;

    detect_kernel<<<1, 256>>>(ei);
    zero_cnt_kernel<<<(N_NODES + 255) / 256, 256>>>();
    hist_kernel<<<eb, 256>>>(ei);
    scan1_kernel<<<SCAN_BLOCKS, 1024>>>();
    scan2_kernel<<<1, 32>>>();
    scan3_kernel<<<SCAN_BLOCKS, 1024>>>();
    fill_kernel<<<eb, 256>>>(ei, ew);

    gemm1_kernel<<<(N_NODES + 255) / 256, 256>>>(x, W1);

    gather_kernel<<<3125, 128>>>(out, 0);   // 12500 warps = 100000 nodes
    mid_kernel<<<(N_NODES + 255) / 256, 256>>>(b1, W2);
    gather_kernel<<<3125, 128>>>(out, 1);
    final_kernel<<<(N_NODES + 255) / 256, 256>>>(out, b2);
}

// round 6
// speedup vs baseline: 1.2493x; 1.0164x over previous
#include <cuda_runtime.h>
#include <cstdint>
#include <math.h>

#define N_NODES 100000
#define N_EDGES 3200000
#define D_FEAT  512
#define HID     16

// ---------------- scratch (device globals; no allocation allowed) ----------
__device__ float g_t1[N_NODES * HID];   // x @ W1
__device__ float g_h1[N_NODES * HID];   // scatter accumulator layer 1
__device__ float g_t2[N_NODES * HID];   // relu(h1+b1) @ W2
__device__ int   g_is64;

// ---------------- helpers --------------------------------------------------
__device__ __forceinline__ unsigned long long ffma2(unsigned long long a,
                                                    unsigned long long b,
                                                    unsigned long long c) {
    unsigned long long d;
    asm("fma.rn.f32x2 %0, %1, %2, %3;" : "=l"(d) : "l"(a), "l"(b), "l"(c));
    return d;
}

// ---------------- edge_index dtype detection (parallel) --------------------
// If int64 with values in [0, N_NODES), every high 32-bit word is 0.
__global__ void detect_kernel(const void* eiv) {
    __shared__ int any32;
    if (threadIdx.x == 0) any32 = 0;
    __syncthreads();
    const int* p = (const int*)eiv;
    int local = 0;
    for (int i = threadIdx.x; i < 2048; i += 256)
        if (p[2 * i + 1] != 0) local = 1;
    if (local) atomicOr(&any32, 1);
    __syncthreads();
    if (threadIdx.x == 0) g_is64 = !any32;
}

// ---------------- zero accumulators ---------------------------------------
__global__ void zero_kernel(float* __restrict__ out) {
    int i = blockIdx.x * blockDim.x + threadIdx.x;
    const int total4 = N_NODES * HID / 4;   // 400000 float4s
    if (i < total4) {
        float4 z = make_float4(0.f, 0.f, 0.f, 0.f);
        ((float4*)g_h1)[i] = z;
        ((float4*)out)[i]  = z;
    }
}

// ---------------- GEMM1: t1 = x @ W1  (100000x512 @ 512x16) ---------------
// Block = 256 threads, 256 rows per block. K tiled by 8.
// FFMA2 (f32x2) packs two output columns per instruction.
#define KT 8
__global__ void gemm1_kernel(const float* __restrict__ x,
                             const float* __restrict__ W1) {
    __shared__ float Ws[D_FEAT * HID];       // 32 KB
    __shared__ float xs[256 * (KT + 1)];     // 9 KB, pad stride 9 (coprime 32)

    const int t = threadIdx.x;
    for (int i = t; i < D_FEAT * HID; i += 256) Ws[i] = W1[i];

    const int row0   = blockIdx.x * 256;
    const int my_row = row0 + t;

    unsigned long long acc[8];
#pragma unroll
    for (int j = 0; j < 8; j++) acc[j] = 0ULL;   // {0.f, 0.f}

    for (int kt = 0; kt < D_FEAT / KT; kt++) {
        const int k0 = kt * KT;
        __syncthreads();
        // stage 256 rows x KT cols, coalesced
#pragma unroll
        for (int i = 0; i < KT; i++) {
            int idx = t + 256 * i;
            int r = idx >> 3;          // KT = 8
            int kk = idx & 7;
            int gr = row0 + r;
            xs[r * (KT + 1) + kk] =
                (gr < N_NODES) ? x[(size_t)gr * D_FEAT + k0 + kk] : 0.0f;
        }
        __syncthreads();

        const float* xrow = xs + t * (KT + 1);
#pragma unroll
        for (int kk = 0; kk < KT; kk++) {
            float xv = xrow[kk];
            unsigned long long xp;
            unsigned int xb = __float_as_uint(xv);
            asm("mov.b64 %0, {%1, %1};" : "=l"(xp) : "r"(xb));
            const ulonglong2* wrow =
                (const ulonglong2*)(Ws + (k0 + kk) * HID);
#pragma unroll
            for (int j2 = 0; j2 < 4; j2++) {
                ulonglong2 wp = wrow[j2];
                acc[2 * j2]     = ffma2(xp, wp.x, acc[2 * j2]);
                acc[2 * j2 + 1] = ffma2(xp, wp.y, acc[2 * j2 + 1]);
            }
        }
    }

    if (my_row < N_NODES) {
        float o[16];
#pragma unroll
        for (int j = 0; j < 8; j++) {
            unsigned int lo, hi;
            asm("mov.b64 {%0, %1}, %2;" : "=r"(lo), "=r"(hi) : "l"(acc[j]));
            o[2 * j]     = __uint_as_float(lo);
            o[2 * j + 1] = __uint_as_float(hi);
        }
        float4* dst = (float4*)(g_t1 + (size_t)my_row * HID);
        dst[0] = make_float4(o[0], o[1], o[2], o[3]);
        dst[1] = make_float4(o[4], o[5], o[6], o[7]);
        dst[2] = make_float4(o[8], o[9], o[10], o[11]);
        dst[3] = make_float4(o[12], o[13], o[14], o[15]);
    }
}

// ---------------- edge scatter: acc[dst] += w * feat[src] ------------------
// One thread per (edge, 4-col chunk): 12.8M units, RED.128 atomics.
// Warp covers 8 edges => 8 gather rows + 8 atomic rows in 64B groups.
__global__ void scatter_kernel(const void* __restrict__ eiv,
                               const float* __restrict__ ew,
                               float* __restrict__ out, int pass) {
    long long u = (long long)blockIdx.x * blockDim.x + threadIdx.x;
    const long long total = (long long)N_EDGES * 4;
    if (u >= total) return;
    int e = (int)(u >> 2);
    int c = (int)(u & 3);

    const float* feat = (pass == 0) ? g_t1 : g_t2;
    float*       acc  = (pass == 0) ? g_h1 : out;

    long long s, d;
    if (!g_is64) {
        const int* ei = (const int*)eiv;
        s = ei[e];
        d = ei[N_EDGES + e];
    } else {
        const long long* ei = (const long long*)eiv;
        s = ei[e];
        d = ei[N_EDGES + e];
    }
    float w = ew[e];
    float4 v = *(const float4*)(feat + s * HID + c * 4);
    float4 m = make_float4(w * v.x, w * v.y, w * v.z, w * v.w);
    atomicAdd((float4*)(acc + d * HID + c * 4), m);
}

// ---------------- mid: t2 = relu(h1 + b1) @ W2 -----------------------------
__global__ void mid_kernel(const float* __restrict__ b1,
                           const float* __restrict__ W2) {
    __shared__ float W2s[HID * HID];
    __shared__ float b1s[HID];
    int t = threadIdx.x;
    if (t < HID * HID) W2s[t] = W2[t];
    if (t < HID) b1s[t] = b1[t];
    __syncthreads();

    int node = blockIdx.x * blockDim.x + t;
    if (node >= N_NODES) return;

    float v[16];
    const float4* src = (const float4*)(g_h1 + (size_t)node * HID);
#pragma unroll
    for (int q = 0; q < 4; q++) {
        float4 f = src[q];
        v[4 * q] = f.x; v[4 * q + 1] = f.y; v[4 * q + 2] = f.z; v[4 * q + 3] = f.w;
    }
#pragma unroll
    for (int i = 0; i < 16; i++) v[i] = fmaxf(v[i] + b1s[i], 0.0f);

    float o[16];
#pragma unroll
    for (int j = 0; j < 16; j++) o[j] = 0.0f;
#pragma unroll
    for (int i = 0; i < 16; i++) {
        float vi = v[i];
#pragma unroll
        for (int j = 0; j < 16; j++) o[j] = fmaf(vi, W2s[i * 16 + j], o[j]);
    }

    float4* dst = (float4*)(g_t2 + (size_t)node * HID);
    dst[0] = make_float4(o[0], o[1], o[2], o[3]);
    dst[1] = make_float4(o[4], o[5], o[6], o[7]);
    dst[2] = make_float4(o[8], o[9], o[10], o[11]);
    dst[3] = make_float4(o[12], o[13], o[14], o[15]);
}

// ---------------- final: out = log_softmax(out + b2) -----------------------
__global__ void final_kernel(float* __restrict__ out,
                             const float* __restrict__ b2) {
    __shared__ float b2s[HID];
    if (threadIdx.x < HID) b2s[threadIdx.x] = b2[threadIdx.x];
    __syncthreads();

    int node = blockIdx.x * blockDim.x + threadIdx.x;
    if (node >= N_NODES) return;

    float o[16];
    float4* p = (float4*)(out + (size_t)node * HID);
#pragma unroll
    for (int q = 0; q < 4; q++) {
        float4 f = p[q];
        o[4 * q]     = f.x + b2s[4 * q];
        o[4 * q + 1] = f.y + b2s[4 * q + 1];
        o[4 * q + 2] = f.z + b2s[4 * q + 2];
        o[4 * q + 3] = f.w + b2s[4 * q + 3];
    }
    float m = o[0];
#pragma unroll
    for (int j = 1; j < 16; j++) m = fmaxf(m, o[j]);
    float ssum = 0.0f;
#pragma unroll
    for (int j = 0; j < 16; j++) ssum += expf(o[j] - m);
    float lse = m + logf(ssum);
#pragma unroll
    for (int j = 0; j < 16; j++) o[j] -= lse;

    p[0] = make_float4(o[0], o[1], o[2], o[3]);
    p[1] = make_float4(o[4], o[5], o[6], o[7]);
    p[2] = make_float4(o[8], o[9], o[10], o[11]);
    p[3] = make_float4(o[12], o[13], o[14], o[15]);
}

// ---------------- launch ---------------------------------------------------
extern "C" void kernel_launch(void* const* d_in, const int* in_sizes, int n_in,
                              void* d_out, int out_size) {
    const float* x  = (const float*)d_in[0];
    const void*  ei = d_in[1];
    const float* ew = (const float*)d_in[2];
    const float* W1 = (const float*)d_in[3];
    const float* b1 = (const float*)d_in[4];
    const float* W2 = (const float*)d_in[5];
    const float* b2 = (const float*)d_in[6];
    float* out = (float*)d_out;

    detect_kernel<<<1, 256>>>(ei);
    zero_kernel<<<(N_NODES * HID / 4 + 255) / 256, 256>>>(out);
    gemm1_kernel<<<(N_NODES + 255) / 256, 256>>>(x, W1);

    const int scat_blocks = (int)(((long long)N_EDGES * 4 + 255) / 256);
    scatter_kernel<<<scat_blocks, 256>>>(ei, ew, out, 0);
    mid_kernel<<<(N_NODES + 255) / 256, 256>>>(b1, W2);
    scatter_kernel<<<scat_blocks, 256>>>(ei, ew, out, 1);
    final_kernel<<<(N_NODES + 255) / 256, 256>>>(out, b2);
}

// round 7
// speedup vs baseline: 1.2682x; 1.0151x over previous
#include <cuda_runtime.h>
#include <cstdint>
#include <math.h>

#define N_NODES 100000
#define N_EDGES 3200000
#define D_FEAT  512
#define HID     16

// ---------------- scratch (device globals; no allocation allowed) ----------
__device__ float g_t1[N_NODES * HID];   // x @ W1
__device__ float g_h1[N_NODES * HID];   // scatter accumulator layer 1
__device__ float g_t2[N_NODES * HID];   // relu(h1+b1) @ W2
__device__ int   g_is64;

// ---------------- helpers --------------------------------------------------
__device__ __forceinline__ unsigned long long ffma2(unsigned long long a,
                                                    unsigned long long b,
                                                    unsigned long long c) {
    unsigned long long d;
    asm("fma.rn.f32x2 %0, %1, %2, %3;" : "=l"(d) : "l"(a), "l"(b), "l"(c));
    return d;
}

// ---------------- edge_index dtype detection (parallel) --------------------
__global__ void detect_kernel(const void* eiv) {
    __shared__ int any32;
    if (threadIdx.x == 0) any32 = 0;
    __syncthreads();
    const int* p = (const int*)eiv;
    int local = 0;
    for (int i = threadIdx.x; i < 2048; i += 256)
        if (p[2 * i + 1] != 0) local = 1;
    if (local) atomicOr(&any32, 1);
    __syncthreads();
    if (threadIdx.x == 0) g_is64 = !any32;
}

// ---------------- zero accumulators (quarter q of 4) -----------------------
__global__ void zero_kernel(float* __restrict__ out, int q) {
    const int quarter4 = N_NODES * HID / 16;   // 100000 float4s per quarter
    int i = q * quarter4 + blockIdx.x * blockDim.x + threadIdx.x;
    float4 z = make_float4(0.f, 0.f, 0.f, 0.f);
    ((float4*)g_h1)[i] = z;
    ((float4*)out)[i]  = z;
}

// ---------------- GEMM1: t1 = x @ W1  (100000x512 @ 512x16) ---------------
// 256 threads, 256 rows/block, K tiled by 8. FFMA2 packs two output cols.
// xs pitch = 12 floats: 16B-aligned rows, conflict-free LDS.128 on compute.
#define KT 8
#define XPITCH 12
__global__ void gemm1_kernel(const float* __restrict__ x,
                             const float* __restrict__ W1) {
    __shared__ float Ws[D_FEAT * HID];        // 32 KB
    __shared__ float xs[256 * XPITCH];        // 12 KB

    const int t = threadIdx.x;
    for (int i = t; i < D_FEAT * HID; i += 256) Ws[i] = W1[i];

    const int row0   = blockIdx.x * 256;
    const int my_row = row0 + t;

    unsigned long long acc[8];
#pragma unroll
    for (int j = 0; j < 8; j++) acc[j] = 0ULL;

    for (int kt = 0; kt < D_FEAT / KT; kt++) {
        const int k0 = kt * KT;
        __syncthreads();
        // stage 256 rows x 8 cols via LDG.128: 512 float4, 2 per thread
#pragma unroll
        for (int i = 0; i < 2; i++) {
            int idx  = t + 256 * i;       // 0..511
            int r    = idx >> 1;
            int half = idx & 1;
            int gr   = row0 + r;
            float4 v = make_float4(0.f, 0.f, 0.f, 0.f);
            if (gr < N_NODES)
                v = *(const float4*)(x + (size_t)gr * D_FEAT + k0 + half * 4);
            *(float4*)(xs + r * XPITCH + half * 4) = v;
        }
        __syncthreads();

#pragma unroll
        for (int h = 0; h < 2; h++) {
            float4 xv = *(const float4*)(xs + t * XPITCH + h * 4);
            float xe[4] = {xv.x, xv.y, xv.z, xv.w};
#pragma unroll
            for (int j = 0; j < 4; j++) {
                unsigned long long xp;
                unsigned int xb = __float_as_uint(xe[j]);
                asm("mov.b64 %0, {%1, %1};" : "=l"(xp) : "r"(xb));
                const ulonglong2* wrow =
                    (const ulonglong2*)(Ws + (k0 + h * 4 + j) * HID);
#pragma unroll
                for (int j2 = 0; j2 < 4; j2++) {
                    ulonglong2 wp = wrow[j2];
                    acc[2 * j2]     = ffma2(xp, wp.x, acc[2 * j2]);
                    acc[2 * j2 + 1] = ffma2(xp, wp.y, acc[2 * j2 + 1]);
                }
            }
        }
    }

    if (my_row < N_NODES) {
        float o[16];
#pragma unroll
        for (int j = 0; j < 8; j++) {
            unsigned int lo, hi;
            asm("mov.b64 {%0, %1}, %2;" : "=r"(lo), "=r"(hi) : "l"(acc[j]));
            o[2 * j]     = __uint_as_float(lo);
            o[2 * j + 1] = __uint_as_float(hi);
        }
        float4* dst = (float4*)(g_t1 + (size_t)my_row * HID);
        dst[0] = make_float4(o[0], o[1], o[2], o[3]);
        dst[1] = make_float4(o[4], o[5], o[6], o[7]);
        dst[2] = make_float4(o[8], o[9], o[10], o[11]);
        dst[3] = make_float4(o[12], o[13], o[14], o[15]);
    }
}

// ---------------- edge scatter: acc[dst] += w * feat[src] ------------------
// One thread per (edge, 4-col chunk): proven best config (R1/R6).
__global__ void scatter_kernel(const void* __restrict__ eiv,
                               const float* __restrict__ ew,
                               float* __restrict__ out, int pass) {
    long long u = (long long)blockIdx.x * blockDim.x + threadIdx.x;
    const long long total = (long long)N_EDGES * 4;
    if (u >= total) return;
    int e = (int)(u >> 2);
    int c = (int)(u & 3);

    const float* feat = (pass == 0) ? g_t1 : g_t2;
    float*       acc  = (pass == 0) ? g_h1 : out;

    long long s, d;
    if (!g_is64) {
        const int* ei = (const int*)eiv;
        s = ei[e];
        d = ei[N_EDGES + e];
    } else {
        const long long* ei = (const long long*)eiv;
        s = ei[e];
        d = ei[N_EDGES + e];
    }
    float w = ew[e];
    float4 v = *(const float4*)(feat + s * HID + c * 4);
    float4 m = make_float4(w * v.x, w * v.y, w * v.z, w * v.w);
    atomicAdd((float4*)(acc + d * HID + c * 4), m);
}

// ---------------- mid: t2 = relu(h1 + b1) @ W2 -----------------------------
__global__ void mid_kernel(const float* __restrict__ b1,
                           const float* __restrict__ W2) {
    __shared__ float W2s[HID * HID];
    __shared__ float b1s[HID];
    int t = threadIdx.x;
    if (t < HID * HID) W2s[t] = W2[t];
    if (t < HID) b1s[t] = b1[t];
    __syncthreads();

    int node = blockIdx.x * blockDim.x + t;
    if (node >= N_NODES) return;

    float v[16];
    const float4* src = (const float4*)(g_h1 + (size_t)node * HID);
#pragma unroll
    for (int q = 0; q < 4; q++) {
        float4 f = src[q];
        v[4 * q] = f.x; v[4 * q + 1] = f.y; v[4 * q + 2] = f.z; v[4 * q + 3] = f.w;
    }
#pragma unroll
    for (int i = 0; i < 16; i++) v[i] = fmaxf(v[i] + b1s[i], 0.0f);

    float o[16];
#pragma unroll
    for (int j = 0; j < 16; j++) o[j] = 0.0f;
#pragma unroll
    for (int i = 0; i < 16; i++) {
        float vi = v[i];
#pragma unroll
        for (int j = 0; j < 16; j++) o[j] = fmaf(vi, W2s[i * 16 + j], o[j]);
    }

    float4* dst = (float4*)(g_t2 + (size_t)node * HID);
    dst[0] = make_float4(o[0], o[1], o[2], o[3]);
    dst[1] = make_float4(o[4], o[5], o[6], o[7]);
    dst[2] = make_float4(o[8], o[9], o[10], o[11]);
    dst[3] = make_float4(o[12], o[13], o[14], o[15]);
}

// ---------------- final: out = log_softmax(out + b2) -----------------------
__global__ void final_kernel(float* __restrict__ out,
                             const float* __restrict__ b2) {
    __shared__ float b2s[HID];
    if (threadIdx.x < HID) b2s[threadIdx.x] = b2[threadIdx.x];
    __syncthreads();

    int node = blockIdx.x * blockDim.x + threadIdx.x;
    if (node >= N_NODES) return;

    float o[16];
    float4* p = (float4*)(out + (size_t)node * HID);
#pragma unroll
    for (int q = 0; q < 4; q++) {
        float4 f = p[q];
        o[4 * q]     = f.x + b2s[4 * q];
        o[4 * q + 1] = f.y + b2s[4 * q + 1];
        o[4 * q + 2] = f.z + b2s[4 * q + 2];
        o[4 * q + 3] = f.w + b2s[4 * q + 3];
    }
    float m = o[0];
#pragma unroll
    for (int j = 1; j < 16; j++) m = fmaxf(m, o[j]);
    float ssum = 0.0f;
#pragma unroll
    for (int j = 0; j < 16; j++) ssum += expf(o[j] - m);
    float lse = m + logf(ssum);
#pragma unroll
    for (int j = 0; j < 16; j++) o[j] -= lse;

    p[0] = make_float4(o[0], o[1], o[2], o[3]);
    p[1] = make_float4(o[4], o[5], o[6], o[7]);
    p[2] = make_float4(o[8], o[9], o[10], o[11]);
    p[3] = make_float4(o[12], o[13], o[14], o[15]);
}

// ---------------- launch ---------------------------------------------------
// Launch order puts gemm1 at index 5 so ncu (-s 5 -c 1) profiles it.
extern "C" void kernel_launch(void* const* d_in, const int* in_sizes, int n_in,
                              void* d_out, int out_size) {
    const float* x  = (const float*)d_in[0];
    const void*  ei = d_in[1];
    const float* ew = (const float*)d_in[2];
    const float* W1 = (const float*)d_in[3];
    const float* b1 = (const float*)d_in[4];
    const float* W2 = (const float*)d_in[5];
    const float* b2 = (const float*)d_in[6];
    float* out = (float*)d_out;

    const int zb = (N_NODES * HID / 16) / 250;  // 400 blocks of 250? -> use 256
    detect_kernel<<<1, 256>>>(ei);                          // 0
    zero_kernel<<<(N_NODES * HID / 16 + 249) / 250, 250>>>(out, 0);  // 1
    zero_kernel<<<(N_NODES * HID / 16 + 249) / 250, 250>>>(out, 1);  // 2
    zero_kernel<<<(N_NODES * HID / 16 + 249) / 250, 250>>>(out, 2);  // 3
    zero_kernel<<<(N_NODES * HID / 16 + 249) / 250, 250>>>(out, 3);  // 4
    gemm1_kernel<<<(N_NODES + 255) / 256, 256>>>(x, W1);             // 5 <- profiled

    const int scat_blocks = (int)(((long long)N_EDGES * 4 + 255) / 256);
    scatter_kernel<<<scat_blocks, 256>>>(ei, ew, out, 0);
    mid_kernel<<<(N_NODES + 255) / 256, 256>>>(b1, W2);
    scatter_kernel<<<scat_blocks, 256>>>(ei, ew, out, 1);
    final_kernel<<<(N_NODES + 255) / 256, 256>>>(out, b2);
    (void)zb;
}

// round 10
// speedup vs baseline: 1.5029x; 1.1851x over previous
#include <cuda_runtime.h>
#include <cstdint>
#include <math.h>

#define N_NODES 100000
#define N_EDGES 3200000
#define D_FEAT  512
#define HID     16

// gemm1 tiling
#define TILE_ROWS 256
#define TPB_G     64
#define RPT       4          // rows per thread
#define XPITCH    36         // x-tile pitch (floats): conflict-free float4 LDS
#define GSMEM_FLOATS (D_FEAT * HID + TILE_ROWS * XPITCH)   // 8192 + 9216
#define GSMEM_BYTES  (GSMEM_FLOATS * 4)                    // 69632 B

// ---------------- scratch (device globals; no allocation allowed) ----------
__device__ float g_t1[N_NODES * HID];   // x @ W1
__device__ float g_h1[N_NODES * HID];   // scatter accumulator layer 1
__device__ float g_t2[N_NODES * HID];   // relu(h1+b1) @ W2
__device__ int   g_is64;

// ---------------- helpers --------------------------------------------------
__device__ __forceinline__ unsigned long long ffma2(unsigned long long a,
                                                    unsigned long long b,
                                                    unsigned long long c) {
    unsigned long long d;
    asm("fma.rn.f32x2 %0, %1, %2, %3;" : "=l"(d) : "l"(a), "l"(b), "l"(c));
    return d;
}

// ---------------- edge_index dtype detection (parallel) --------------------
__global__ void detect_kernel(const void* eiv) {
    __shared__ int any32;
    if (threadIdx.x == 0) any32 = 0;
    __syncthreads();
    const int* p = (const int*)eiv;
    int local = 0;
    for (int i = threadIdx.x; i < 2048; i += 256)
        if (p[2 * i + 1] != 0) local = 1;
    if (local) atomicOr(&any32, 1);
    __syncthreads();
    if (threadIdx.x == 0) g_is64 = !any32;
}

// ---------------- zero accumulators ---------------------------------------
__global__ void zero_kernel(float* __restrict__ out) {
    int i = blockIdx.x * blockDim.x + threadIdx.x;
    const int total4 = N_NODES * HID / 4;
    if (i < total4) {
        float4 z = make_float4(0.f, 0.f, 0.f, 0.f);
        ((float4*)g_h1)[i] = z;
        ((float4*)out)[i]  = z;
    }
}

// ---------------- GEMM1: t1 = x @ W1, register-blocked 4 rows/thread -------
__global__ void __launch_bounds__(TPB_G) gemm1_kernel(
        const float* __restrict__ x, const float* __restrict__ W1) {
    extern __shared__ float sm[];
    float* Ws = sm;                       // 8192 floats (full W1)
    float* xs = sm + D_FEAT * HID;        // 256 x 36 floats

    const int t = threadIdx.x;

    // load all of W1, coalesced float4
    for (int i = t; i < D_FEAT * HID / 4; i += TPB_G)
        ((float4*)Ws)[i] = ((const float4*)W1)[i];

    const int row0 = blockIdx.x * TILE_ROWS;

    unsigned long long acc[RPT][8];
#pragma unroll
    for (int r = 0; r < RPT; r++)
#pragma unroll
        for (int j = 0; j < 8; j++) acc[r][j] = 0ULL;

    for (int kt = 0; kt < D_FEAT / 32; kt++) {
        const int k0 = kt * 32;
        __syncthreads();
        // stage 256 rows x 32 floats (128B/row) -- coalesced
#pragma unroll
        for (int i = 0; i < 32; i++) {
            int v   = i * TPB_G + t;       // 0..2047 float4 slots
            int lr  = v >> 3;              // local row
            int sub = v & 7;               // float4 within row
            int gr  = row0 + lr;
            if (gr >= N_NODES) gr = N_NODES - 1;   // clamp (dup read ok)
            float4 val = *(const float4*)(x + (size_t)gr * D_FEAT + k0 + sub * 4);
            *(float4*)(xs + lr * XPITCH + sub * 4) = val;
        }
        __syncthreads();

#pragma unroll
        for (int kk4 = 0; kk4 < 8; kk4++) {
            float4 xv[RPT];
#pragma unroll
            for (int r = 0; r < RPT; r++)
                xv[r] = *(const float4*)(xs + (t + TPB_G * r) * XPITCH + kk4 * 4);
#pragma unroll
            for (int kk = 0; kk < 4; kk++) {
                const ulonglong2* wrow =
                    (const ulonglong2*)(Ws + (k0 + kk4 * 4 + kk) * HID);
                ulonglong2 w0 = wrow[0], w1 = wrow[1];
                ulonglong2 w2 = wrow[2], w3 = wrow[3];
#pragma unroll
                for (int r = 0; r < RPT; r++) {
                    float xe = ((const float*)&xv[r])[kk];
                    unsigned long long xp;
                    unsigned int xb = __float_as_uint(xe);
                    asm("mov.b64 %0, {%1, %1};" : "=l"(xp) : "r"(xb));
                    acc[r][0] = ffma2(xp, w0.x, acc[r][0]);
                    acc[r][1] = ffma2(xp, w0.y, acc[r][1]);
                    acc[r][2] = ffma2(xp, w1.x, acc[r][2]);
                    acc[r][3] = ffma2(xp, w1.y, acc[r][3]);
                    acc[r][4] = ffma2(xp, w2.x, acc[r][4]);
                    acc[r][5] = ffma2(xp, w2.y, acc[r][5]);
                    acc[r][6] = ffma2(xp, w3.x, acc[r][6]);
                    acc[r][7] = ffma2(xp, w3.y, acc[r][7]);
                }
            }
        }
    }

#pragma unroll
    for (int r = 0; r < RPT; r++) {
        int gr = row0 + t + TPB_G * r;
        if (gr < N_NODES) {
            float o[16];
#pragma unroll
            for (int j = 0; j < 8; j++) {
                unsigned int lo, hi;
                asm("mov.b64 {%0, %1}, %2;" : "=r"(lo), "=r"(hi) : "l"(acc[r][j]));
                o[2 * j]     = __uint_as_float(lo);
                o[2 * j + 1] = __uint_as_float(hi);
            }
            float4* dst = (float4*)(g_t1 + (size_t)gr * HID);
            dst[0] = make_float4(o[0], o[1], o[2], o[3]);
            dst[1] = make_float4(o[4], o[5], o[6], o[7]);
            dst[2] = make_float4(o[8], o[9], o[10], o[11]);
            dst[3] = make_float4(o[12], o[13], o[14], o[15]);
        }
    }
}

// ---------------- edge scatter: acc[dst] += w * feat[src] ------------------
// One thread per (edge, 4-col chunk): proven best config.
__global__ void scatter_kernel(const void* __restrict__ eiv,
                               const float* __restrict__ ew,
                               float* __restrict__ out, int pass) {
    long long u = (long long)blockIdx.x * blockDim.x + threadIdx.x;
    const long long total = (long long)N_EDGES * 4;
    if (u >= total) return;
    int e = (int)(u >> 2);
    int c = (int)(u & 3);

    const float* feat = (pass == 0) ? g_t1 : g_t2;
    float*       acc  = (pass == 0) ? g_h1 : out;

    long long s, d;
    if (!g_is64) {
        const int* ei = (const int*)eiv;
        s = ei[e];
        d = ei[N_EDGES + e];
    } else {
        const long long* ei = (const long long*)eiv;
        s = ei[e];
        d = ei[N_EDGES + e];
    }
    float w = ew[e];
    float4 v = *(const float4*)(feat + s * HID + c * 4);
    float4 m = make_float4(w * v.x, w * v.y, w * v.z, w * v.w);
    atomicAdd((float4*)(acc + d * HID + c * 4), m);
}

// ---------------- mid: t2 = relu(h1 + b1) @ W2 -----------------------------
__global__ void mid_kernel(const float* __restrict__ b1,
                           const float* __restrict__ W2) {
    __shared__ float W2s[HID * HID];
    __shared__ float b1s[HID];
    int t = threadIdx.x;
    if (t < HID * HID) W2s[t] = W2[t];
    if (t < HID) b1s[t] = b1[t];
    __syncthreads();

    int node = blockIdx.x * blockDim.x + t;
    if (node >= N_NODES) return;

    float v[16];
    const float4* src = (const float4*)(g_h1 + (size_t)node * HID);
#pragma unroll
    for (int q = 0; q < 4; q++) {
        float4 f = src[q];
        v[4 * q] = f.x; v[4 * q + 1] = f.y; v[4 * q + 2] = f.z; v[4 * q + 3] = f.w;
    }
#pragma unroll
    for (int i = 0; i < 16; i++) v[i] = fmaxf(v[i] + b1s[i], 0.0f);

    float o[16];
#pragma unroll
    for (int j = 0; j < 16; j++) o[j] = 0.0f;
#pragma unroll
    for (int i = 0; i < 16; i++) {
        float vi = v[i];
#pragma unroll
        for (int j = 0; j < 16; j++) o[j] = fmaf(vi, W2s[i * 16 + j], o[j]);
    }

    float4* dst = (float4*)(g_t2 + (size_t)node * HID);
    dst[0] = make_float4(o[0], o[1], o[2], o[3]);
    dst[1] = make_float4(o[4], o[5], o[6], o[7]);
    dst[2] = make_float4(o[8], o[9], o[10], o[11]);
    dst[3] = make_float4(o[12], o[13], o[14], o[15]);
}

// ---------------- final: out = log_softmax(out + b2) -----------------------
__global__ void final_kernel(float* __restrict__ out,
                             const float* __restrict__ b2) {
    __shared__ float b2s[HID];
    if (threadIdx.x < HID) b2s[threadIdx.x] = b2[threadIdx.x];
    __syncthreads();

    int node = blockIdx.x * blockDim.x + threadIdx.x;
    if (node >= N_NODES) return;

    float o[16];
    float4* p = (float4*)(out + (size_t)node * HID);
#pragma unroll
    for (int q = 0; q < 4; q++) {
        float4 f = p[q];
        o[4 * q]     = f.x + b2s[4 * q];
        o[4 * q + 1] = f.y + b2s[4 * q + 1];
        o[4 * q + 2] = f.z + b2s[4 * q + 2];
        o[4 * q + 3] = f.w + b2s[4 * q + 3];
    }
    float m = o[0];
#pragma unroll
    for (int j = 1; j < 16; j++) m = fmaxf(m, o[j]);
    float ssum = 0.0f;
#pragma unroll
    for (int j = 0; j < 16; j++) ssum += expf(o[j] - m);
    float lse = m + logf(ssum);
#pragma unroll
    for (int j = 0; j < 16; j++) o[j] -= lse;

    p[0] = make_float4(o[0], o[1], o[2], o[3]);
    p[1] = make_float4(o[4], o[5], o[6], o[7]);
    p[2] = make_float4(o[8], o[9], o[10], o[11]);
    p[3] = make_float4(o[12], o[13], o[14], o[15]);
}

// ---------------- launch ---------------------------------------------------
extern "C" void kernel_launch(void* const* d_in, const int* in_sizes, int n_in,
                              void* d_out, int out_size) {
    const float* x  = (const float*)d_in[0];
    const void*  ei = d_in[1];
    const float* ew = (const float*)d_in[2];
    const float* W1 = (const float*)d_in[3];
    const float* b1 = (const float*)d_in[4];
    const float* W2 = (const float*)d_in[5];
    const float* b2 = (const float*)d_in[6];
    float* out = (float*)d_out;

    static int smem_set = 0;
    if (!smem_set) {
        cudaFuncSetAttribute(gemm1_kernel,
                             cudaFuncAttributeMaxDynamicSharedMemorySize,
                             GSMEM_BYTES);
        smem_set = 1;
    }

    detect_kernel<<<1, 256>>>(ei);
    zero_kernel<<<(N_NODES * HID / 4 + 255) / 256, 256>>>(out);
    gemm1_kernel<<<(N_NODES + TILE_ROWS - 1) / TILE_ROWS, TPB_G,
                   GSMEM_BYTES>>>(x, W1);

    const int scat_blocks = (int)(((long long)N_EDGES * 4 + 255) / 256);
    scatter_kernel<<<scat_blocks, 256>>>(ei, ew, out, 0);
    mid_kernel<<<(N_NODES + 255) / 256, 256>>>(b1, W2);
    scatter_kernel<<<scat_blocks, 256>>>(ei, ew, out, 1);
    final_kernel<<<(N_NODES + 255) / 256, 256>>>(out, b2);
}